// round 3
// baseline (speedup 1.0000x reference)
#include <cuda_runtime.h>
#include <math.h>

#define NBATCH 16
#define LPAD 1280
#define LIN 1250
#define DM 64
#define NH 4
#define DH 16
#define NR 4        // hash rounds
#define BSZ 64      // bucket chunk size
#define NB 20       // buckets per round
#define NCH 80      // NR*NB chunks
#define BHH 64      // NBATCH*NH
#define MR 20480    // NBATCH*LPAD
#define FF 256

// ---------------- scratch (device globals; no allocation allowed) ----------------
__device__ float g_x1[MR*DM];
__device__ float g_x2[MR*DM];
__device__ float g_xn[MR*DM];
__device__ float g_qk[BHH*LPAD*DH];
__device__ float g_v [BHH*LPAD*DH];
__device__ unsigned char g_bkt[BHH*NR*LPAD];
__device__ int   g_cnt[BHH*NR*8*NB];
__device__ int   g_off[BHH*NR*8*NB];
__device__ short g_sj [BHH*NR*LPAD];
__device__ float g_o  [BHH*NR*LPAD*DH];
__device__ float g_lse[BHH*NR*LPAD];
__device__ float g_att[MR*DM];
__device__ float g_ffh[MR*FF];

// ---------------- embed: x = pad(wave^T) @ in_w + in_b ----------------
__global__ void k_embed(const float* __restrict__ wave, const float* __restrict__ in_w,
                        const float* __restrict__ in_b, float* __restrict__ x1,
                        float* __restrict__ x2){
  int gid = blockIdx.x*256 + threadIdx.x;       // 16*1280*64 total
  int d = gid & 63;
  int t = (gid >> 6) % LPAD;
  int b = gid / (LPAD*64);
  float val = in_b[d];
  if (t < LIN)
    val += wave[b*2*LIN + t]*in_w[d] + wave[b*2*LIN + LIN + t]*in_w[64+d];
  x1[gid] = val; x2[gid] = val;
}

// ---------------- layernorm over D=64 (warp per row) ----------------
__global__ void k_ln(const float* __restrict__ x, const float* __restrict__ g,
                     const float* __restrict__ b, float* __restrict__ y){
  int row  = blockIdx.x*4 + (threadIdx.x >> 5);
  int lane = threadIdx.x & 31;
  const float* xr = x + (size_t)row*DM;
  float a0 = xr[lane], a1 = xr[lane+32];
  float s = a0 + a1;
  #pragma unroll
  for (int o=16;o>0;o>>=1) s += __shfl_xor_sync(0xffffffffu, s, o);
  float mean = s * (1.0f/64.0f);
  float d0 = a0-mean, d1 = a1-mean;
  float vs = d0*d0 + d1*d1;
  #pragma unroll
  for (int o=16;o>0;o>>=1) vs += __shfl_xor_sync(0xffffffffu, vs, o);
  float inv = rsqrtf(vs*(1.0f/64.0f) + 1e-5f);
  float* yr = y + (size_t)row*DM;
  yr[lane]    = d0*inv*g[lane]    + b[lane];
  yr[lane+32] = d1*inv*g[lane+32] + b[lane+32];
}

// ---------------- fused qk/v GEMM (M x 64 @ 64 x 64, head-split output) ----------------
__global__ void k_gemm_qkv(const float* __restrict__ X, const float* __restrict__ Wq,
                           const float* __restrict__ Wv, float* __restrict__ qk,
                           float* __restrict__ v){
  __shared__ float Xs[32][65];
  __shared__ float Wqs[4096];
  __shared__ float Wvs[4096];
  int tid = threadIdx.x;
  int row0 = blockIdx.x*32;
  for (int i=tid;i<2048;i+=256){ int r=i>>6,k=i&63; Xs[r][k] = X[(size_t)(row0+r)*64 + k]; }
  for (int i=tid;i<4096;i+=256){ Wqs[i]=Wq[i]; Wvs[i]=Wv[i]; }
  __syncthreads();
  int tx = tid & 15, ty = tid >> 4;
  float aq[2][4]={{0.f,0.f,0.f,0.f},{0.f,0.f,0.f,0.f}};
  float av[2][4]={{0.f,0.f,0.f,0.f},{0.f,0.f,0.f,0.f}};
  #pragma unroll 4
  for (int k=0;k<64;k++){
    float x0 = Xs[ty*2][k], x1 = Xs[ty*2+1][k];
    #pragma unroll
    for (int cc=0;cc<4;cc++){
      float wq = Wqs[k*64 + tx + cc*16];
      float wv = Wvs[k*64 + tx + cc*16];
      aq[0][cc] += x0*wq; aq[1][cc] += x1*wq;
      av[0][cc] += x0*wv; av[1][cc] += x1*wv;
    }
  }
  #pragma unroll
  for (int rr=0;rr<2;rr++){
    int m = row0 + ty*2 + rr;
    int b = m / LPAD, t = m % LPAD;
    #pragma unroll
    for (int cc=0;cc<4;cc++){
      size_t oidx = ((size_t)(b*NH+cc)*LPAD + t)*DH + tx;  // head cc, dim tx
      qk[oidx] = aq[rr][cc];
      v[oidx]  = av[rr][cc];
    }
  }
}

__device__ __forceinline__ float gelu_f(float x){
  return 0.5f*x*(1.0f + erff(x*0.7071067811865476f));
}

// ---------------- generic GEMM: Y = epi(X@W + bias)  (MODE 0: Y+=val, 1: Y=gelu(val)) ----
template<int N, int K, int MODE>
__global__ void k_gemm(const float* __restrict__ X, const float* __restrict__ W,
                       const float* __restrict__ bias, float* __restrict__ Y){
  constexpr int KC = K/64, NC = N/64;
  __shared__ float Xs[32][65];
  __shared__ float Ws[4096];
  int tid = threadIdx.x;
  int tx = tid & 15, ty = tid >> 4;
  int row0 = blockIdx.x*32;
  float acc[NC][2][4];
  #pragma unroll
  for (int a=0;a<NC;a++){
    #pragma unroll
    for(int rr=0;rr<2;rr++){
      #pragma unroll
      for(int cc=0;cc<4;cc++) acc[a][rr][cc]=0.f;
    }
  }
  for (int kc=0;kc<KC;kc++){
    __syncthreads();
    for (int i=tid;i<2048;i+=256){ int r=i>>6,k=i&63; Xs[r][k]=X[(size_t)(row0+r)*K + kc*64 + k]; }
    for (int nc=0;nc<NC;nc++){
      __syncthreads();
      for (int i=tid;i<4096;i+=256){ int k=i>>6,c=i&63; Ws[i]=W[(size_t)(kc*64+k)*N + nc*64 + c]; }
      __syncthreads();
      #pragma unroll 4
      for (int k=0;k<64;k++){
        float x0=Xs[ty*2][k], x1=Xs[ty*2+1][k];
        #pragma unroll
        for (int cc=0;cc<4;cc++){
          float w=Ws[k*64 + tx + cc*16];
          acc[nc][0][cc]+=x0*w; acc[nc][1][cc]+=x1*w;
        }
      }
    }
  }
  #pragma unroll
  for (int nc=0;nc<NC;nc++){
    #pragma unroll
    for (int rr=0;rr<2;rr++){
      int m = row0 + ty*2 + rr;
      #pragma unroll
      for (int cc=0;cc<4;cc++){
        int c = nc*64 + tx + cc*16;
        float val = acc[nc][rr][cc] + bias[c];
        if (MODE==0) Y[(size_t)m*N + c] += val;
        else         Y[(size_t)m*N + c] = gelu_f(val);
      }
    }
  }
}

// ---------------- LSH hashing: argmax over [proj, -proj] ----------------
__global__ void k_hash(const float* __restrict__ qk, const float* __restrict__ rot,
                       unsigned char* __restrict__ bkt){
  __shared__ float rs[640];                      // rot (16,4,10)
  int tid = threadIdx.x;                         // 128
  for (int i=tid;i<640;i+=128) rs[i]=rot[i];
  __syncthreads();
  int t  = blockIdx.x*128 + tid;
  int bh = blockIdx.y;
  const float4* qr = reinterpret_cast<const float4*>(qk + ((size_t)bh*LPAD + t)*DH);
  float q[16];
  #pragma unroll
  for (int i=0;i<4;i++){ float4 f4=qr[i]; q[4*i]=f4.x; q[4*i+1]=f4.y; q[4*i+2]=f4.z; q[4*i+3]=f4.w; }
  #pragma unroll
  for (int r=0;r<NR;r++){
    float p[10];
    #pragma unroll
    for (int i=0;i<10;i++){
      float s=0.f;
      #pragma unroll
      for (int f=0;f<16;f++) s += q[f]*rs[f*40 + r*10 + i];
      p[i]=s;
    }
    float best=-3.402823e38f; int bi=0;
    #pragma unroll
    for (int idx=0; idx<20; idx++){
      float val = (idx<10)? p[idx] : -p[idx-10];
      if (val>best){best=val;bi=idx;}           // first-max tie-break like jnp.argmax
    }
    bkt[((size_t)bh*NR + r)*LPAD + t] = (unsigned char)bi;
  }
}

// ---------------- counting sort (stable): count / prefix / scatter ----------------
__global__ void k_count(const unsigned char* __restrict__ bkt, int* __restrict__ cnt){
  __shared__ int c[NB][256];
  int tid = threadIdx.x;
  int g = blockIdx.x*256 + tid;                 // 2048 = bh*32 + r*8 + seg
  int seg = g & 7, r = (g>>3)&3, bh = g>>5;
  #pragma unroll
  for (int b=0;b<NB;b++) c[b][tid]=0;
  const unsigned char* p = bkt + ((size_t)bh*NR + r)*LPAD + seg*160;
  for (int i=0;i<160;i++) c[p[i]][tid]++;
  int* outp = cnt + ((size_t)((bh*NR+r)*8 + seg))*NB;
  #pragma unroll
  for (int b=0;b<NB;b++) outp[b]=c[b][tid];
}

__global__ void k_prefix(const int* __restrict__ cnt, int* __restrict__ off){
  int bh = threadIdx.x;                         // 64 threads
  int run=0;
  for (int r=0;r<NR;r++)
    for (int b=0;b<NB;b++)                      // global bucket (r,b) ascending
      for (int seg=0;seg<8;seg++){
        int idx = ((bh*NR+r)*8+seg)*NB + b;
        off[idx]=run; run += cnt[idx];
      }
}

__global__ void k_scatter(const unsigned char* __restrict__ bkt, const int* __restrict__ off,
                          short* __restrict__ sj){
  __shared__ int c[NB][256];
  int tid = threadIdx.x;
  int g = blockIdx.x*256 + tid;
  int seg = g & 7, r = (g>>3)&3, bh = g>>5;
  const int* op = off + ((size_t)((bh*NR+r)*8+seg))*NB;
  #pragma unroll
  for (int b=0;b<NB;b++) c[b][tid]=op[b];
  const unsigned char* p = bkt + ((size_t)bh*NR+r)*LPAD + seg*160;
  short* sjb = sj + (size_t)bh*NR*LPAD;
  int basej = r*LPAD + seg*160;
  for (int i=0;i<160;i++){
    int b = p[i];
    int s = c[b][tid]++;
    sjb[s] = (short)(basej + i);
  }
}

// ---------------- chunked LSH attention with look-back, flash softmax ----------------
__global__ void k_attn(const float* __restrict__ qk, const float* __restrict__ v,
                       const short* __restrict__ sj, float* __restrict__ o,
                       float* __restrict__ lse){
  __shared__ float Ks[128][17];
  __shared__ float Vs[128][17];
  __shared__ int   tks[128];
  int c = blockIdx.x, bh = blockIdx.y, tid = threadIdx.x;  // 64 threads
  const short* sjb = sj + (size_t)bh*NR*LPAD;
  int jq = sjb[c*BSZ + tid];
  int tq = jq % LPAD, rq = jq / LPAD;
  float q[16];
  { const float4* qr = reinterpret_cast<const float4*>(qk + ((size_t)bh*LPAD + tq)*DH);
    #pragma unroll
    for (int i=0;i<4;i++){ float4 f4=qr[i]; q[4*i]=f4.x; q[4*i+1]=f4.y; q[4*i+2]=f4.z; q[4*i+3]=f4.w; } }
  int prev = (c + NCH - 1) % NCH;
  for (int kk=tid; kk<128; kk+=64){
    int cc = (kk<64)? c : prev;
    int jk = sjb[cc*BSZ + (kk&63)];
    int tk = jk % LPAD;
    float kv[16];
    { const float4* kr = reinterpret_cast<const float4*>(qk + ((size_t)bh*LPAD + tk)*DH);
      #pragma unroll
      for (int i=0;i<4;i++){ float4 f4=kr[i]; kv[4*i]=f4.x; kv[4*i+1]=f4.y; kv[4*i+2]=f4.z; kv[4*i+3]=f4.w; } }
    float ss=0.f;
    #pragma unroll
    for (int f=0;f<16;f++) ss += kv[f]*kv[f];
    float inv = 1.0f / fmaxf(sqrtf(ss), 1e-12f);
    #pragma unroll
    for (int f=0;f<16;f++) Ks[kk][f]=kv[f]*inv;
    { const float4* vr = reinterpret_cast<const float4*>(v + ((size_t)bh*LPAD + tk)*DH);
      #pragma unroll
      for (int i=0;i<4;i++){ float4 f4=vr[i]; Vs[kk][4*i]=f4.x; Vs[kk][4*i+1]=f4.y; Vs[kk][4*i+2]=f4.z; Vs[kk][4*i+3]=f4.w; } }
    tks[kk]=tk;
  }
  __syncthreads();
  float m=-3.0e38f, l=0.f, acc[16];
  #pragma unroll
  for (int f=0;f<16;f++) acc[f]=0.f;
  for (int j=0;j<128;j++){
    float d=0.f;
    #pragma unroll
    for (int f=0;f<16;f++) d += q[f]*Ks[j][f];
    d *= 0.25f;                                  // DH^-0.5
    if (tks[j]==tq) d = -50000.0f;               // SELF_ATTN_VAL
    if (d>m){
      float sc=__expf(m-d);
      l*=sc;
      #pragma unroll
      for (int f=0;f<16;f++) acc[f]*=sc;
      m=d;
    }
    float p=__expf(d-m);
    l += p;
    #pragma unroll
    for (int f=0;f<16;f++) acc[f] += p*Vs[j][f];
  }
  float invl = 1.0f/l;
  float* op = o + ((size_t)(bh*NR + rq)*LPAD + tq)*DH;   // scatter == undo_sort
  #pragma unroll
  for (int f=0;f<16;f++) op[f]=acc[f]*invl;
  lse[(size_t)(bh*NR+rq)*LPAD + tq] = m + logf(l);
}

// ---------------- combine hash rounds by softmax of their lse ----------------
__global__ void k_combine(const float* __restrict__ o, const float* __restrict__ lse,
                          float* __restrict__ att){
  int gid = blockIdx.x*256 + threadIdx.x;        // BHH*LPAD*16 total
  int f = gid & 15;
  int tok = gid >> 4;
  int bh = tok / LPAD, t = tok % LPAD;
  float ls[NR];
  #pragma unroll
  for (int r=0;r<NR;r++) ls[r]=lse[(size_t)(bh*NR+r)*LPAD + t];
  float mx = fmaxf(fmaxf(ls[0],ls[1]), fmaxf(ls[2],ls[3]));
  float w[NR], s=0.f;
  #pragma unroll
  for (int r=0;r<NR;r++){ w[r]=__expf(ls[r]-mx); s+=w[r]; }
  float invs = 1.f/s;
  float outv=0.f;
  #pragma unroll
  for (int r=0;r<NR;r++) outv += w[r]*o[((size_t)(bh*NR+r)*LPAD + t)*DH + f];
  int b = bh >> 2, h = bh & 3;
  att[((size_t)b*LPAD + t)*DM + h*DH + f] = outv*invs;
}

// ---------------- final: y = ((x1+x2)*0.5) @ out_w + out_b, trim to 1250 ----------------
__global__ void k_final(const float* __restrict__ x1, const float* __restrict__ x2,
                        const float* __restrict__ ow, const float* __restrict__ ob,
                        float* __restrict__ y){
  int row  = blockIdx.x*4 + (threadIdx.x>>5);    // 16*1250 rows
  int lane = threadIdx.x & 31;
  int b = row / LIN, t = row % LIN;
  size_t base = ((size_t)b*LPAD + t)*DM;
  float s = (x1[base+lane]+x2[base+lane])*0.5f*ow[lane]
          + (x1[base+lane+32]+x2[base+lane+32])*0.5f*ow[lane+32];
  #pragma unroll
  for (int o2=16;o2>0;o2>>=1) s += __shfl_xor_sync(0xffffffffu, s, o2);
  if (lane==0) y[row] = s + ob[0];
}

// ---------------- host launcher ----------------
extern "C" void kernel_launch(void* const* d_in, const int* in_sizes, int n_in,
                              void* d_out, int out_size){
  const float* wave  = (const float*)d_in[0];
  const float* in_w  = (const float*)d_in[1];
  const float* in_b  = (const float*)d_in[2];
  const float* ln1_g = (const float*)d_in[3];
  const float* ln1_b = (const float*)d_in[4];
  const float* wqk   = (const float*)d_in[5];
  const float* wv    = (const float*)d_in[6];
  const float* wo_w  = (const float*)d_in[7];
  const float* wo_b  = (const float*)d_in[8];
  const float* rot   = (const float*)d_in[9];
  const float* ln2_g = (const float*)d_in[10];
  const float* ln2_b = (const float*)d_in[11];
  const float* w1    = (const float*)d_in[12];
  const float* b1    = (const float*)d_in[13];
  const float* w2    = (const float*)d_in[14];
  const float* b2    = (const float*)d_in[15];
  const float* out_w = (const float*)d_in[16];
  const float* out_b = (const float*)d_in[17];

  float *x1,*x2,*xn,*qkp,*vp,*op,*lsp,*attp,*ffp;
  unsigned char* bktp; int *cntp,*offp; short* sjp;
  cudaGetSymbolAddress((void**)&x1,  g_x1);
  cudaGetSymbolAddress((void**)&x2,  g_x2);
  cudaGetSymbolAddress((void**)&xn,  g_xn);
  cudaGetSymbolAddress((void**)&qkp, g_qk);
  cudaGetSymbolAddress((void**)&vp,  g_v);
  cudaGetSymbolAddress((void**)&bktp,g_bkt);
  cudaGetSymbolAddress((void**)&cntp,g_cnt);
  cudaGetSymbolAddress((void**)&offp,g_off);
  cudaGetSymbolAddress((void**)&sjp, g_sj);
  cudaGetSymbolAddress((void**)&op,  g_o);
  cudaGetSymbolAddress((void**)&lsp, g_lse);
  cudaGetSymbolAddress((void**)&attp,g_att);
  cudaGetSymbolAddress((void**)&ffp, g_ffh);

  k_embed<<<5120,256>>>(wave, in_w, in_b, x1, x2);

  for (int i=0;i<4;i++){
    k_ln<<<5120,128>>>(x2, ln1_g+i*64, ln1_b+i*64, xn);
    k_gemm_qkv<<<640,256>>>(xn, wqk+i*4096, wv+i*4096, qkp, vp);
    k_hash<<<dim3(10,64),128>>>(qkp, rot+i*640, bktp);
    k_count<<<8,256>>>(bktp, cntp);
    k_prefix<<<1,64>>>(cntp, offp);
    k_scatter<<<8,256>>>(bktp, offp, sjp);
    k_attn<<<dim3(80,64),64>>>(qkp, vp, sjp, op, lsp);
    k_combine<<<5120,256>>>(op, lsp, attp);
    k_gemm<64,64,0><<<640,256>>>(attp, wo_w+i*4096, wo_b+i*64, x1);
    k_ln<<<5120,128>>>(x1, ln2_g+i*64, ln2_b+i*64, xn);
    k_gemm<256,64,1><<<640,256>>>(xn, w1+i*16384, b1+i*256, ffp);
    k_gemm<64,256,0><<<640,256>>>(ffp, w2+i*16384, b2+i*64, x2);
  }

  k_final<<<5000,128>>>(x1, x2, out_w, out_b, (float*)d_out);
}

// round 5
// speedup vs baseline: 1.1656x; 1.1656x over previous
#include <cuda_runtime.h>
#include <math.h>

#define NBATCH 16
#define LPAD 1280
#define LIN 1250
#define DM 64
#define NH 4
#define DH 16
#define NR 4        // hash rounds
#define BSZ 64      // bucket chunk size
#define NB 20       // buckets per round
#define NCH 80      // NR*NB chunks
#define BHH 64      // NBATCH*NH
#define MR 20480    // NBATCH*LPAD
#define FF 256

typedef unsigned long long ull;

__device__ __forceinline__ ull pack2(float lo, float hi){
  ull r; asm("mov.b64 %0,{%1,%2};" : "=l"(r) : "f"(lo), "f"(hi)); return r;
}
__device__ __forceinline__ void unpack2(ull a, float& lo, float& hi){
  asm("mov.b64 {%0,%1},%2;" : "=f"(lo), "=f"(hi) : "l"(a));
}
__device__ __forceinline__ void fma2(ull& d, ull a, ull b){
  asm("fma.rn.f32x2 %0,%1,%2,%0;" : "+l"(d) : "l"(a), "l"(b));
}
__device__ __forceinline__ void mul2(ull& d, ull a, ull b){
  asm("mul.rn.f32x2 %0,%1,%2;" : "=l"(d) : "l"(a), "l"(b));
}
__device__ __forceinline__ float hsum2(ull a){
  float lo, hi; unpack2(a, lo, hi); return lo + hi;
}

// ---------------- scratch (device globals; no allocation allowed) ----------------
__device__ float g_x1[MR*DM];
__device__ float g_x2[MR*DM];
__device__ float g_xn[MR*DM];
__device__ float g_qk[BHH*LPAD*DH];
__device__ float g_v [BHH*LPAD*DH];
__device__ unsigned char g_bkt[BHH*NR*LPAD];
__device__ int   g_cnt[BHH*NR*8*NB];
__device__ int   g_off[BHH*NR*8*NB];
__device__ short g_sj [BHH*NR*LPAD];
__device__ float g_o  [BHH*NR*LPAD*DH];
__device__ float g_lse[BHH*NR*LPAD];
__device__ float g_att[MR*DM];
__device__ float g_ffh[MR*FF];

// ---------------- embed: x = pad(wave^T) @ in_w + in_b ----------------
__global__ void k_embed(const float* __restrict__ wave, const float* __restrict__ in_w,
                        const float* __restrict__ in_b, float* __restrict__ x1,
                        float* __restrict__ x2){
  int gid = blockIdx.x*256 + threadIdx.x;       // 16*1280*64 total
  int d = gid & 63;
  int t = (gid >> 6) % LPAD;
  int b = gid / (LPAD*64);
  float val = in_b[d];
  if (t < LIN)
    val += wave[b*2*LIN + t]*in_w[d] + wave[b*2*LIN + LIN + t]*in_w[64+d];
  x1[gid] = val; x2[gid] = val;
}

// ---------------- layernorm over D=64 (warp per row) ----------------
__global__ void k_ln(const float* __restrict__ x, const float* __restrict__ g,
                     const float* __restrict__ b, float* __restrict__ y){
  int row  = blockIdx.x*4 + (threadIdx.x >> 5);
  int lane = threadIdx.x & 31;
  const float* xr = x + (size_t)row*DM;
  float a0 = xr[lane], a1 = xr[lane+32];
  float s = a0 + a1;
  #pragma unroll
  for (int o=16;o>0;o>>=1) s += __shfl_xor_sync(0xffffffffu, s, o);
  float mean = s * (1.0f/64.0f);
  float d0 = a0-mean, d1 = a1-mean;
  float vs = d0*d0 + d1*d1;
  #pragma unroll
  for (int o=16;o>0;o>>=1) vs += __shfl_xor_sync(0xffffffffu, vs, o);
  float inv = rsqrtf(vs*(1.0f/64.0f) + 1e-5f);
  float* yr = y + (size_t)row*DM;
  yr[lane]    = d0*inv*g[lane]    + b[lane];
  yr[lane+32] = d1*inv*g[lane+32] + b[lane+32];
}

__device__ __forceinline__ float gelu_f(float x){
  return 0.5f*x*(1.0f + erff(x*0.7071067811865476f));
}

// ---------------- generic GEMM: Y = epi(X@W + bias), 64x64 tiles, f32x2 -------------
// MODE 0: Y += val (residual);  MODE 1: Y = gelu(val)
template<int N, int K, int MODE>
__global__ __launch_bounds__(256) void k_gemm(const float* __restrict__ X,
                       const float* __restrict__ W,
                       const float* __restrict__ bias, float* __restrict__ Y){
  __shared__ float Xs[64][68];   // Xs[r][k]
  __shared__ float Ws[64][68];   // Ws[c][k] (transposed)
  int tid = threadIdx.x;
  int row0 = blockIdx.x*64;
  int col0 = blockIdx.y*64;
  int tx = tid & 15, ty = tid >> 4;      // c0 = 4*tx, r0 = 4*ty
  ull acc[4][4];
  #pragma unroll
  for (int i=0;i<4;i++)
    #pragma unroll
    for (int j=0;j<4;j++) acc[i][j] = 0ull;

  for (int kc=0; kc<K/64; kc++){
    __syncthreads();
    { // X tile: 64 rows x 64 k
      int r = tid & 63, q = tid >> 6;
      const float4* src = (const float4*)(X + (size_t)(row0+r)*K + kc*64) + q*4;
      float4* dst = (float4*)&Xs[r][q*16];
      dst[0]=src[0]; dst[1]=src[1]; dst[2]=src[2]; dst[3]=src[3];
    }
    { // W tile transposed
      int k = tid & 63, q = tid >> 6;
      const float* wr = W + (size_t)(kc*64+k)*N + col0 + q*16;
      #pragma unroll
      for (int i=0;i<4;i++){
        float4 w = ((const float4*)wr)[i];
        int c = q*16 + 4*i;
        Ws[c+0][k]=w.x; Ws[c+1][k]=w.y; Ws[c+2][k]=w.z; Ws[c+3][k]=w.w;
      }
    }
    __syncthreads();
    #pragma unroll
    for (int kq=0; kq<16; kq++){
      ull xv[4][2], wv[4][2];
      #pragma unroll
      for (int i=0;i<4;i++){
        ulonglong2 t = *(const ulonglong2*)&Xs[4*ty+i][kq*4];
        xv[i][0]=t.x; xv[i][1]=t.y;
      }
      #pragma unroll
      for (int j=0;j<4;j++){
        ulonglong2 t = *(const ulonglong2*)&Ws[4*tx+j][kq*4];
        wv[j][0]=t.x; wv[j][1]=t.y;
      }
      #pragma unroll
      for (int i=0;i<4;i++)
        #pragma unroll
        for (int j=0;j<4;j++){
          fma2(acc[i][j], xv[i][0], wv[j][0]);
          fma2(acc[i][j], xv[i][1], wv[j][1]);
        }
    }
  }
  float4 b4 = ((const float4*)(bias + col0))[tx];
  #pragma unroll
  for (int i=0;i<4;i++){
    int row = row0 + 4*ty + i;
    float4 o;
    o.x = hsum2(acc[i][0]) + b4.x;
    o.y = hsum2(acc[i][1]) + b4.y;
    o.z = hsum2(acc[i][2]) + b4.z;
    o.w = hsum2(acc[i][3]) + b4.w;
    float4* yp = (float4*)(Y + (size_t)row*N + col0);
    if (MODE==0){
      float4 prev = yp[tx];
      o.x += prev.x; o.y += prev.y; o.z += prev.z; o.w += prev.w;
      yp[tx] = o;
    } else {
      o.x = gelu_f(o.x); o.y = gelu_f(o.y); o.z = gelu_f(o.z); o.w = gelu_f(o.w);
      yp[tx] = o;
    }
  }
}

// ---------------- fused qk/v GEMM (64x64 tiles, head-split output) ----------------
__global__ __launch_bounds__(256) void k_gemm_qkv(const float* __restrict__ X,
                           const float* __restrict__ Wq,
                           const float* __restrict__ Wv, float* __restrict__ qk,
                           float* __restrict__ v){
  __shared__ float Xs[64][68];
  __shared__ float Wqs[64][68];
  __shared__ float Wvs[64][68];
  int tid = threadIdx.x;
  int row0 = blockIdx.x*64;
  int tx = tid & 15, ty = tid >> 4;
  { int r = tid & 63, q = tid >> 6;
    const float4* src = (const float4*)(X + (size_t)(row0+r)*64) + q*4;
    float4* dst = (float4*)&Xs[r][q*16];
    dst[0]=src[0]; dst[1]=src[1]; dst[2]=src[2]; dst[3]=src[3]; }
  { int k = tid & 63, q = tid >> 6;
    const float* wr = Wq + (size_t)k*64 + q*16;
    const float* vr = Wv + (size_t)k*64 + q*16;
    #pragma unroll
    for (int i=0;i<4;i++){
      float4 w = ((const float4*)wr)[i];
      float4 wv2 = ((const float4*)vr)[i];
      int c = q*16 + 4*i;
      Wqs[c+0][k]=w.x; Wqs[c+1][k]=w.y; Wqs[c+2][k]=w.z; Wqs[c+3][k]=w.w;
      Wvs[c+0][k]=wv2.x; Wvs[c+1][k]=wv2.y; Wvs[c+2][k]=wv2.z; Wvs[c+3][k]=wv2.w;
    } }
  __syncthreads();
  ull accq[4][4], accv[4][4];
  #pragma unroll
  for (int i=0;i<4;i++)
    #pragma unroll
    for (int j=0;j<4;j++){ accq[i][j]=0ull; accv[i][j]=0ull; }
  #pragma unroll
  for (int kq=0; kq<16; kq++){
    ull xv[4][2], wq2[4][2], wv2[4][2];
    #pragma unroll
    for (int i=0;i<4;i++){
      ulonglong2 t = *(const ulonglong2*)&Xs[4*ty+i][kq*4];
      xv[i][0]=t.x; xv[i][1]=t.y;
    }
    #pragma unroll
    for (int j=0;j<4;j++){
      ulonglong2 a = *(const ulonglong2*)&Wqs[4*tx+j][kq*4];
      wq2[j][0]=a.x; wq2[j][1]=a.y;
      ulonglong2 b = *(const ulonglong2*)&Wvs[4*tx+j][kq*4];
      wv2[j][0]=b.x; wv2[j][1]=b.y;
    }
    #pragma unroll
    for (int i=0;i<4;i++)
      #pragma unroll
      for (int j=0;j<4;j++){
        fma2(accq[i][j], xv[i][0], wq2[j][0]);
        fma2(accq[i][j], xv[i][1], wq2[j][1]);
        fma2(accv[i][j], xv[i][0], wv2[j][0]);
        fma2(accv[i][j], xv[i][1], wv2[j][1]);
      }
  }
  int head = tx >> 2, d0 = 4*(tx & 3);
  #pragma unroll
  for (int i=0;i<4;i++){
    int m = row0 + 4*ty + i;
    int b = m / LPAD, t = m % LPAD;
    size_t base = ((size_t)(b*NH + head)*LPAD + t)*DH + d0;
    float4 oq, ov;
    oq.x=hsum2(accq[i][0]); oq.y=hsum2(accq[i][1]); oq.z=hsum2(accq[i][2]); oq.w=hsum2(accq[i][3]);
    ov.x=hsum2(accv[i][0]); ov.y=hsum2(accv[i][1]); ov.z=hsum2(accv[i][2]); ov.w=hsum2(accv[i][3]);
    *(float4*)(qk + base) = oq;
    *(float4*)(v  + base) = ov;
  }
}

// ---------------- LSH hashing + per-segment histogram (fused) ----------------
__global__ void k_hashcount(const float* __restrict__ qk, const float* __restrict__ rot,
                            unsigned char* __restrict__ bkt, int* __restrict__ cnt){
  __shared__ float rs[640];                      // rot (16,4,10)
  __shared__ int c[NR][NB];
  int tid = threadIdx.x;                         // 160
  int seg = blockIdx.x, bh = blockIdx.y;
  for (int i=tid;i<640;i+=160) rs[i]=rot[i];
  if (tid < NR*NB) ((int*)c)[tid] = 0;
  __syncthreads();
  int t = seg*160 + tid;
  const float4* qr = reinterpret_cast<const float4*>(qk + ((size_t)bh*LPAD + t)*DH);
  float q[16];
  #pragma unroll
  for (int i=0;i<4;i++){ float4 f4=qr[i]; q[4*i]=f4.x; q[4*i+1]=f4.y; q[4*i+2]=f4.z; q[4*i+3]=f4.w; }
  #pragma unroll
  for (int r=0;r<NR;r++){
    float p[10];
    #pragma unroll
    for (int i=0;i<10;i++){
      float s=0.f;
      #pragma unroll
      for (int f=0;f<16;f++) s += q[f]*rs[f*40 + r*10 + i];
      p[i]=s;
    }
    float best=-3.402823e38f; int bi=0;
    #pragma unroll
    for (int idx=0; idx<20; idx++){
      float val = (idx<10)? p[idx] : -p[idx-10];
      if (val>best){best=val;bi=idx;}           // first-max tie-break like jnp.argmax
    }
    bkt[((size_t)bh*NR + r)*LPAD + t] = (unsigned char)bi;
    atomicAdd(&c[r][bi], 1);
  }
  __syncthreads();
  if (tid < NR*NB){
    int r = tid / NB, b = tid % NB;
    cnt[((size_t)((bh*NR+r)*8 + seg))*NB + b] = c[r][b];
  }
}

// ---------------- parallel exclusive scan per bh (640 elements) ----------------
__global__ void k_prefix(const int* __restrict__ cnt, int* __restrict__ off){
  __shared__ int ws[20];
  int bh = blockIdx.x;
  int i = threadIdx.x;                           // 640
  int r = i/160, b = (i%160)/8, seg = i%8;       // scan order (r,b,seg)
  int idx = ((bh*NR + r)*8 + seg)*NB + b;
  int v = cnt[idx];
  int lane = i & 31, w = i >> 5;
  int s = v;
  #pragma unroll
  for (int o=1;o<32;o<<=1){ int t=__shfl_up_sync(0xffffffffu, s, o); if (lane>=o) s+=t; }
  if (lane==31) ws[w]=s;
  __syncthreads();
  if (i < 32){
    int t = (i<20)? ws[i] : 0;
    #pragma unroll
    for (int o=1;o<32;o<<=1){ int u=__shfl_up_sync(0xffffffffu, t, o); if (i>=o) t+=u; }
    if (i<20) ws[i]=t;
  }
  __syncthreads();
  int base = (w>0)? ws[w-1] : 0;
  off[idx] = base + s - v;
}

// ---------------- stable scatter ----------------
__global__ void k_scatter(const unsigned char* __restrict__ bkt, const int* __restrict__ off,
                          short* __restrict__ sj){
  __shared__ int c[NB][256];
  int tid = threadIdx.x;
  int g = blockIdx.x*256 + tid;
  int seg = g & 7, r = (g>>3)&3, bh = g>>5;
  const int* op = off + ((size_t)((bh*NR+r)*8+seg))*NB;
  #pragma unroll
  for (int b=0;b<NB;b++) c[b][tid]=op[b];
  const unsigned char* p = bkt + ((size_t)bh*NR+r)*LPAD + seg*160;
  short* sjb = sj + (size_t)bh*NR*LPAD;
  int basej = r*LPAD + seg*160;
  #pragma unroll 4
  for (int i=0;i<160;i++){
    int b = p[i];
    int s = c[b][tid]++;
    sjb[s] = (short)(basej + i);
  }
}

// ---------------- chunked LSH attention, flash softmax, f32x2 ----------------
__global__ void k_attn(const float* __restrict__ qk, const float* __restrict__ v,
                       const short* __restrict__ sj, float* __restrict__ o,
                       float* __restrict__ lse){
  __shared__ float Ks[128][16];
  __shared__ float Vs[128][16];
  __shared__ int   tks[128];
  int c = blockIdx.x, bh = blockIdx.y, tid = threadIdx.x;  // 64 threads
  const short* sjb = sj + (size_t)bh*NR*LPAD;
  int jq = sjb[c*BSZ + tid];
  int tq = jq % LPAD, rq = jq / LPAD;
  ull qv[8];
  { const ulonglong2* qr = reinterpret_cast<const ulonglong2*>(qk + ((size_t)bh*LPAD + tq)*DH);
    #pragma unroll
    for (int i=0;i<4;i++){ ulonglong2 u=qr[i]; qv[2*i]=u.x; qv[2*i+1]=u.y; } }
  int prev = (c + NCH - 1) % NCH;
  for (int kk=tid; kk<128; kk+=64){
    int cc = (kk<64)? c : prev;
    int jk = sjb[cc*BSZ + (kk&63)];
    int tk = jk % LPAD;
    float kvv[16];
    { const float4* kr = reinterpret_cast<const float4*>(qk + ((size_t)bh*LPAD + tk)*DH);
      #pragma unroll
      for (int i=0;i<4;i++){ float4 f4=kr[i]; kvv[4*i]=f4.x; kvv[4*i+1]=f4.y; kvv[4*i+2]=f4.z; kvv[4*i+3]=f4.w; } }
    float ss=0.f;
    #pragma unroll
    for (int f=0;f<16;f++) ss += kvv[f]*kvv[f];
    float inv = 1.0f / fmaxf(sqrtf(ss), 1e-12f);
    float4* kd = (float4*)&Ks[kk][0];
    #pragma unroll
    for (int i=0;i<4;i++){
      float4 f4; f4.x=kvv[4*i]*inv; f4.y=kvv[4*i+1]*inv; f4.z=kvv[4*i+2]*inv; f4.w=kvv[4*i+3]*inv;
      kd[i]=f4;
    }
    { const float4* vr = reinterpret_cast<const float4*>(v + ((size_t)bh*LPAD + tk)*DH);
      float4* vd = (float4*)&Vs[kk][0];
      #pragma unroll
      for (int i=0;i<4;i++) vd[i]=vr[i];
    }
    tks[kk]=tk;
  }
  __syncthreads();
  float m=-3.0e38f, l=0.f;
  ull acc2[8];
  #pragma unroll
  for (int f=0;f<8;f++) acc2[f]=0ull;
  #pragma unroll 2
  for (int j=0;j<128;j++){
    const ulonglong2* kr = (const ulonglong2*)&Ks[j][0];
    ull d2 = 0ull;
    #pragma unroll
    for (int i=0;i<4;i++){
      ulonglong2 u = kr[i];
      fma2(d2, qv[2*i],   u.x);
      fma2(d2, qv[2*i+1], u.y);
    }
    float d = hsum2(d2) * 0.25f;                 // DH^-0.5
    if (tks[j]==tq) d = -50000.0f;               // SELF_ATTN_VAL
    if (d>m){
      float sc=__expf(m-d);
      l*=sc;
      ull sc2 = pack2(sc,sc);
      #pragma unroll
      for (int f=0;f<8;f++) mul2(acc2[f], acc2[f], sc2);
      m=d;
    }
    float p=__expf(d-m);
    l += p;
    ull p2 = pack2(p,p);
    const ulonglong2* vr = (const ulonglong2*)&Vs[j][0];
    #pragma unroll
    for (int i=0;i<4;i++){
      ulonglong2 u = vr[i];
      fma2(acc2[2*i],   p2, u.x);
      fma2(acc2[2*i+1], p2, u.y);
    }
  }
  float invl = 1.0f/l;
  float out[16];
  #pragma unroll
  for (int f=0;f<8;f++) unpack2(acc2[f], out[2*f], out[2*f+1]);
  float4* op = (float4*)(o + ((size_t)(bh*NR + rq)*LPAD + tq)*DH);  // scatter == undo_sort
  #pragma unroll
  for (int i=0;i<4;i++){
    float4 f4; f4.x=out[4*i]*invl; f4.y=out[4*i+1]*invl; f4.z=out[4*i+2]*invl; f4.w=out[4*i+3]*invl;
    op[i]=f4;
  }
  lse[(size_t)(bh*NR+rq)*LPAD + tq] = m + logf(l);
}

// ---------------- combine hash rounds by softmax of their lse ----------------
__global__ void k_combine(const float* __restrict__ o, const float* __restrict__ lse,
                          float* __restrict__ att){
  int gid = blockIdx.x*256 + threadIdx.x;        // BHH*LPAD*16 total
  int f = gid & 15;
  int tok = gid >> 4;
  int bh = tok / LPAD, t = tok % LPAD;
  float ls[NR];
  #pragma unroll
  for (int r=0;r<NR;r++) ls[r]=lse[(size_t)(bh*NR+r)*LPAD + t];
  float mx = fmaxf(fmaxf(ls[0],ls[1]), fmaxf(ls[2],ls[3]));
  float w[NR], s=0.f;
  #pragma unroll
  for (int r=0;r<NR;r++){ w[r]=__expf(ls[r]-mx); s+=w[r]; }
  float invs = 1.f/s;
  float outv=0.f;
  #pragma unroll
  for (int r=0;r<NR;r++) outv += w[r]*o[((size_t)(bh*NR+r)*LPAD + t)*DH + f];
  int b = bh >> 2, h = bh & 3;
  att[((size_t)b*LPAD + t)*DM + h*DH + f] = outv*invs;
}

// ---------------- final: y = ((x1+x2)*0.5) @ out_w + out_b, trim to 1250 ----------------
__global__ void k_final(const float* __restrict__ x1, const float* __restrict__ x2,
                        const float* __restrict__ ow, const float* __restrict__ ob,
                        float* __restrict__ y){
  int row  = blockIdx.x*4 + (threadIdx.x>>5);    // 16*1250 rows
  int lane = threadIdx.x & 31;
  int b = row / LIN, t = row % LIN;
  size_t base = ((size_t)b*LPAD + t)*DM;
  float s = (x1[base+lane]+x2[base+lane])*0.5f*ow[lane]
          + (x1[base+lane+32]+x2[base+lane+32])*0.5f*ow[lane+32];
  #pragma unroll
  for (int o2=16;o2>0;o2>>=1) s += __shfl_xor_sync(0xffffffffu, s, o2);
  if (lane==0) y[row] = s + ob[0];
}

// ---------------- host launcher ----------------
extern "C" void kernel_launch(void* const* d_in, const int* in_sizes, int n_in,
                              void* d_out, int out_size){
  const float* wave  = (const float*)d_in[0];
  const float* in_w  = (const float*)d_in[1];
  const float* in_b  = (const float*)d_in[2];
  const float* ln1_g = (const float*)d_in[3];
  const float* ln1_b = (const float*)d_in[4];
  const float* wqk   = (const float*)d_in[5];
  const float* wv    = (const float*)d_in[6];
  const float* wo_w  = (const float*)d_in[7];
  const float* wo_b  = (const float*)d_in[8];
  const float* rot   = (const float*)d_in[9];
  const float* ln2_g = (const float*)d_in[10];
  const float* ln2_b = (const float*)d_in[11];
  const float* w1    = (const float*)d_in[12];
  const float* b1    = (const float*)d_in[13];
  const float* w2    = (const float*)d_in[14];
  const float* b2    = (const float*)d_in[15];
  const float* out_w = (const float*)d_in[16];
  const float* out_b = (const float*)d_in[17];

  float *x1,*x2,*xn,*qkp,*vp,*op,*lsp,*attp,*ffp;
  unsigned char* bktp; int *cntp,*offp; short* sjp;
  cudaGetSymbolAddress((void**)&x1,  g_x1);
  cudaGetSymbolAddress((void**)&x2,  g_x2);
  cudaGetSymbolAddress((void**)&xn,  g_xn);
  cudaGetSymbolAddress((void**)&qkp, g_qk);
  cudaGetSymbolAddress((void**)&vp,  g_v);
  cudaGetSymbolAddress((void**)&bktp,g_bkt);
  cudaGetSymbolAddress((void**)&cntp,g_cnt);
  cudaGetSymbolAddress((void**)&offp,g_off);
  cudaGetSymbolAddress((void**)&sjp, g_sj);
  cudaGetSymbolAddress((void**)&op,  g_o);
  cudaGetSymbolAddress((void**)&lsp, g_lse);
  cudaGetSymbolAddress((void**)&attp,g_att);
  cudaGetSymbolAddress((void**)&ffp, g_ffh);

  k_embed<<<5120,256>>>(wave, in_w, in_b, x1, x2);

  for (int i=0;i<4;i++){
    k_ln<<<5120,128>>>(x2, ln1_g+i*64, ln1_b+i*64, xn);
    k_gemm_qkv<<<320,256>>>(xn, wqk+i*4096, wv+i*4096, qkp, vp);
    k_hashcount<<<dim3(8,64),160>>>(qkp, rot+i*640, bktp, cntp);
    k_prefix<<<64,640>>>(cntp, offp);
    k_scatter<<<8,256>>>(bktp, offp, sjp);
    k_attn<<<dim3(80,64),64>>>(qkp, vp, sjp, op, lsp);
    k_combine<<<5120,256>>>(op, lsp, attp);
    k_gemm<64,64,0><<<dim3(320,1),256>>>(attp, wo_w+i*4096, wo_b+i*64, x1);
    k_ln<<<5120,128>>>(x1, ln2_g+i*64, ln2_b+i*64, xn);
    k_gemm<256,64,1><<<dim3(320,4),256>>>(xn, w1+i*16384, b1+i*256, ffp);
    k_gemm<64,256,0><<<dim3(320,1),256>>>(ffp, w2+i*16384, b2+i*64, x2);
  }

  k_final<<<5000,128>>>(x1, x2, out_w, out_b, (float*)d_out);
}